// round 11
// baseline (speedup 1.0000x reference)
#include <cuda_runtime.h>
#include <math.h>

#define Wd 256
#define Hd 256
#define NP (Wd*Hd)
#define NG 1024
#define MF 50
#define NTILES 256     // 16x16 tiles of 16x16 px
#define GROUPS 6
#define GCH 25         // channels per group
#define NQ 7           // float4 per staged candidate: 28 floats (25 used, 3 pad)
#define CCHUNK 32
#define CAP 64         // per-tile candidate capacity (expected ~16)
#define NITEMS (NTILES*GROUPS)   // 1536
#define NBLOCKS 304              // 152 SM * 2 CTAs

__device__ int g_work;           // zero-init; reset by the last stealer

struct SMem {
    float cx[NG], cy[NG], h1[NG], c2[NG], h3[NG], op[NG];  // 24 KB
    unsigned short list[NTILES][CAP];                       // 32 KB
    int cnt[NTILES];                                        // 1 KB
    float4 sfeat[CCHUNK][NQ];                               // 3.5 KB
    int item;
};

__device__ __forceinline__ void fma2(unsigned long long& acc,
                                     unsigned long long a2,
                                     unsigned long long f2) {
    asm("fma.rn.f32x2 %0, %1, %2, %0;" : "+l"(acc) : "l"(a2), "l"(f2));
}

__global__ void __launch_bounds__(256, 2)
fused_kernel(const float* __restrict__ xyz,
             const float* __restrict__ chol,
             const float* __restrict__ opac,
             const float* __restrict__ feats,
             const int* __restrict__ cid_ptr,
             float* __restrict__ out) {
    extern __shared__ char smem_raw[];
    SMem* sm = (SMem*)smem_raw;
    int t = threadIdx.x;

    // ---- Phase 1: per-block redundant binning (no global coordination) ----
    if (t < NTILES) sm->cnt[t] = 0;
    __syncthreads();

    #pragma unroll
    for (int k = 0; k < NG/256; k++) {
        int n = t + k*256;
        float l1 = chol[n*3+0] + 0.5f;
        float l2 = chol[n*3+1];
        float l3 = chol[n*3+2] + 0.5f;
        float a = l1*l1, b = l1*l2, c = l2*l2 + l3*l3;
        float inv = 1.0f / (a*c - b*b);
        float cx = 0.5f*((tanhf(xyz[n*2+0]) + 1.0f)*(float)Wd - 1.0f);
        float cy = 0.5f*((tanhf(xyz[n*2+1]) + 1.0f)*(float)Hd - 1.0f);
        float op = opac[n];
        sm->cx[n] = cx; sm->cy[n] = cy;
        sm->h1[n] = 0.5f*c*inv;          // 0.5*conic1
        sm->c2[n] = -b*inv;              // conic2
        sm->h3[n] = 0.5f*a*inv;          // 0.5*conic3
        sm->op[n] = op;

        // alpha >= 1/255 <=> sigma <= T = ln(255*op); sigma >= 0 (det > 0)
        float T = (op > 0.f) ? logf(255.0f*op) : -1.0f;
        if (T >= 0.f) {
            float rx = sqrtf(fmaxf(0.f, 2.0f*T*a)) + 1.0f;  // sqrt(2T*Sigma_xx)
            float ry = sqrtf(fmaxf(0.f, 2.0f*T*c)) + 1.0f;
            int x0 = max(0,    (int)floorf(cx - rx));
            int x1 = min(Wd-1, (int)ceilf (cx + rx));
            int y0 = max(0,    (int)floorf(cy - ry));
            int y1 = min(Hd-1, (int)ceilf (cy + ry));
            if (x0 <= x1 && y0 <= y1) {
                for (int ty = (y0 >> 4); ty <= (y1 >> 4); ty++)
                    for (int tx = (x0 >> 4); tx <= (x1 >> 4); tx++) {
                        int tl = ty*16 + tx;
                        int slot = atomicAdd(&sm->cnt[tl], 1);
                        if (slot < CAP) sm->list[tl][slot] = (unsigned short)n;
                    }
            }
        }
    }
    __syncthreads();

    // ---- Phase 2: persistent work-stealing render (R5 core) ----
    const float* __restrict__ fbase = feats + (long)cid_ptr[0]*MF*NG*3;

    for (;;) {
        __syncthreads();
        if (t == 0) sm->item = atomicAdd(&g_work, 1);
        __syncthreads();
        int item = sm->item;
        if (item >= NITEMS) {
            // last hand-out resets the counter for the next graph replay
            if (t == 0 && item == NITEMS + NBLOCKS - 1) atomicExch(&g_work, 0);
            return;
        }

        int tile = item & 255;
        int grp  = item >> 8;
        int tx = tile & 15, ty = tile >> 4;
        float px = (float)(tx*16 + (t & 15));
        float py = (float)(ty*16 + (t >> 4));

        unsigned long long acc2[NQ*2];
        #pragma unroll
        for (int k = 0; k < NQ*2; k++) acc2[k] = 0ull;

        int count = min(sm->cnt[tile], CAP);
        const unsigned short* __restrict__ list = sm->list[tile];
        const int chbase = grp * GCH;

        for (int base = 0; base < count; base += CCHUNK) {
            int lim = min(CCHUNK, count - base);
            // stage this group's feature rows straight from gmem (L2-hot)
            for (int i = t; i < lim*(NQ*4); i += 256) {
                int j = i / (NQ*4);
                int c = i - j*(NQ*4);                 // 0..27
                float v = 0.f;
                if (c < GCH) {
                    int ch = chbase + c;
                    int m  = ch / 3;
                    int cc = ch - m*3;
                    int n  = list[base + j];
                    v = fbase[(m*NG + n)*3 + cc];
                }
                ((float*)sm->sfeat)[j*(NQ*4) + c] = v;
            }
            __syncthreads();

            int   n0  = list[base];
            float gcx = sm->cx[n0], gcy = sm->cy[n0];
            float gh1 = sm->h1[n0], gc2 = sm->c2[n0];
            float gh3 = sm->h3[n0], gop = sm->op[n0];
            for (int j = 0; j < lim; j++) {
                float dx = gcx - px;
                float dy = gcy - py;
                float sigma = gh1*dx*dx + gh3*dy*dy + gc2*dx*dy;
                float opj = gop;
                if (j + 1 < lim) {                    // prefetch next params
                    int n1 = list[base + j + 1];
                    gcx = sm->cx[n1]; gcy = sm->cy[n1];
                    gh1 = sm->h1[n1]; gc2 = sm->c2[n1];
                    gh3 = sm->h3[n1]; gop = sm->op[n1];
                }
                float a = 0.f;
                if (sigma >= 0.f) {
                    float al = fminf(0.999f, opj*__expf(-sigma));
                    if (al >= (1.0f/255.0f)) a = al;
                }
                if (__any_sync(0xffffffffu, a != 0.f)) {
                    unsigned long long a2;
                    asm("mov.b64 %0, {%1, %1};" : "=l"(a2) : "f"(a));
                    const ulonglong2* __restrict__ sf =
                        (const ulonglong2*)&sm->sfeat[j][0];
                    #pragma unroll
                    for (int q = 0; q < NQ; q++) {
                        ulonglong2 u = sf[q];                 // LDS.128 bcast
                        fma2(acc2[2*q],   a2, u.x);
                        fma2(acc2[2*q+1], a2, u.y);
                    }
                }
            }
            __syncthreads();
        }

        // out[mc][y][x]; channels [grp*25, grp*25+25), coalesced 128B stores
        float accf[NQ*4];
        #pragma unroll
        for (int k = 0; k < NQ*2; k++)
            asm("mov.b64 {%0, %1}, %2;"
                : "=f"(accf[2*k]), "=f"(accf[2*k+1]) : "l"(acc2[k]));
        int pixBase = (ty*16 + (t >> 4))*Wd + tx*16 + (t & 15);
        float* o = out + chbase*NP + pixBase;
        #pragma unroll
        for (int c = 0; c < GCH; c++)
            o[c*NP] = accf[c];
    }
}

extern "C" void kernel_launch(void* const* d_in, const int* in_sizes, int n_in,
                              void* d_out, int out_size) {
    const float* xyz   = (const float*)d_in[0];
    const float* chol  = (const float*)d_in[1];
    const float* opac  = (const float*)d_in[2];
    const float* feats = (const float*)d_in[3];
    const int*   cid   = (const int*)  d_in[4];
    float* out = (float*)d_out;

    static int smem_set = 0;
    if (!smem_set) {
        cudaFuncSetAttribute(fused_kernel,
                             cudaFuncAttributeMaxDynamicSharedMemorySize,
                             (int)sizeof(SMem));
        smem_set = 1;
    }
    fused_kernel<<<NBLOCKS, 256, sizeof(SMem)>>>(xyz, chol, opac, feats, cid, out);
}